// round 1
// baseline (speedup 1.0000x reference)
#include <cuda_runtime.h>
#include <math.h>

#define IMGS  16
#define H     256
#define W     256
#define NPIX  (H * W)            // 65536
#define TOTAL (IMGS * NPIX)      // 1048576
#define INFV  1.0e6f

// ---- scratch (static __device__ arrays; allocation-free per harness rules) ----
__device__ float  g_fg[TOTAL];     // squared vertical distance, EDT(mask)
__device__ float  g_bg[TOTAL];     // squared vertical distance, EDT(1-mask)
__device__ float  sd_buf[TOTAL];   // unnormalized signed distance
__device__ float  d_maxabs[IMGS];
__device__ int    d_counts[IMGS];
__device__ double d_acc;

// ---------------------------------------------------------------------------
__global__ void init_kernel() {
    int t = threadIdx.x;
    if (t < IMGS) { d_maxabs[t] = 0.0f; d_counts[t] = 0; }
    if (t == 0)   d_acc = 0.0;
}

// ---------------------------------------------------------------------------
// Vertical two-pass scan (both masks in one go). One warp handles 32 columns
// of one image. grid = IMGS * 8 blocks, 32 threads.
__global__ void col_pass_kernel(const float* __restrict__ target) {
    int b     = blockIdx.x >> 3;
    int chunk = blockIdx.x & 7;
    int x     = chunk * 32 + threadIdx.x;

    const float* m  = target + b * NPIX + x;
    float*       gf = g_fg   + b * NPIX + x;
    float*       gb = g_bg   + b * NPIX + x;

    float cf = INFV, cb = INFV;
    int cnt = 0;
    #pragma unroll 8
    for (int y = 0; y < H; y++) {
        float mv = m[y * W];
        bool  fg = (mv > 0.5f);
        cnt += fg ? 1 : 0;
        cf = fminf(fg ? INFV : 0.0f, cf + 1.0f);
        cb = fminf(fg ? 0.0f : INFV, cb + 1.0f);
        gf[y * W] = cf;
        gb[y * W] = cb;
    }
    cf = INFV; cb = INFV;
    #pragma unroll 8
    for (int y = H - 1; y >= 0; y--) {
        float mv = m[y * W];
        bool  fg = (mv > 0.5f);
        cf = fminf(fg ? INFV : 0.0f, cf + 1.0f);
        cb = fminf(fg ? 0.0f : INFV, cb + 1.0f);
        float df = fminf(cf, gf[y * W]);  gf[y * W] = df * df;
        float db = fminf(cb, gb[y * W]);  gb[y * W] = db * db;
    }
    // warp-reduce foreground count
    #pragma unroll
    for (int o = 16; o; o >>= 1) cnt += __shfl_xor_sync(0xffffffffu, cnt, o);
    if (threadIdx.x == 0) atomicAdd(&d_counts[b], cnt);
}

// ---------------------------------------------------------------------------
// Row min-plus: dt2[x] = min_q (g[q] + q^2) + (-2x)*q + x^2.
// One block per (image,row). 256 threads, thread x produces one output.
__global__ void row_pass_kernel() {
    int b    = blockIdx.x >> 8;
    int y    = blockIdx.x & 255;
    int base = b * NPIX + y * W;
    int x    = threadIdx.x;

    __shared__ float hf[W];
    __shared__ float hb[W];
    __shared__ float red[8];

    float q2 = (float)(x * x);              // exact (<= 65025 < 2^24)
    hf[x] = g_fg[base + x] + q2;
    hb[x] = g_bg[base + x] + q2;
    __syncthreads();

    float c  = -2.0f * (float)x;
    float bf = 3.0e38f, bb = 3.0e38f;
    const float4* hf4 = (const float4*)hf;
    const float4* hb4 = (const float4*)hb;

    #pragma unroll
    for (int j = 0; j < W / 4; j++) {
        float4 a = hf4[j];
        float4 d = hb4[j];
        float q0 = (float)(4 * j);
        bf = fminf(bf, fmaf(c, q0,        a.x));
        bf = fminf(bf, fmaf(c, q0 + 1.0f, a.y));
        bf = fminf(bf, fmaf(c, q0 + 2.0f, a.z));
        bf = fminf(bf, fmaf(c, q0 + 3.0f, a.w));
        bb = fminf(bb, fmaf(c, q0,        d.x));
        bb = fminf(bb, fmaf(c, q0 + 1.0f, d.y));
        bb = fminf(bb, fmaf(c, q0 + 2.0f, d.z));
        bb = fminf(bb, fmaf(c, q0 + 3.0f, d.w));
    }

    float x2   = (float)(x * x);
    float dt2f = bf + x2;
    float dt2b = bb + x2;
    float sd   = sqrtf(dt2b) - sqrtf(dt2f);
    sd_buf[base + x] = sd;

    // block max |sd| -> per-image atomic max (non-neg floats order as ints)
    float a = fabsf(sd);
    #pragma unroll
    for (int o = 16; o; o >>= 1) a = fmaxf(a, __shfl_xor_sync(0xffffffffu, a, o));
    if ((x & 31) == 0) red[x >> 5] = a;
    __syncthreads();
    if (x < 8) {
        a = red[x];
        #pragma unroll
        for (int o = 4; o; o >>= 1) a = fmaxf(a, __shfl_xor_sync(0xffu, a, o));
        if (x == 0) atomicMax((int*)&d_maxabs[b], __float_as_int(a));
    }
}

// ---------------------------------------------------------------------------
// Final fused sigmoid * normalized-signed-distance sum (double accumulation).
__global__ void reduce_kernel(const float* __restrict__ pred) {
    __shared__ double wsum[8];
    double s = 0.0;
    int stride = gridDim.x * blockDim.x;
    for (int i = blockIdx.x * blockDim.x + threadIdx.x; i < TOTAL; i += stride) {
        int   b    = i >> 16;
        int   cnt  = d_counts[b];
        bool  valid = (cnt > 0) && (cnt < NPIX);
        float den  = d_maxabs[b] + 1e-6f;
        float p    = pred[i];
        float prob = 1.0f / (1.0f + expf(-p));
        float sd   = sd_buf[i] / den;
        if (valid) s += (double)(prob * sd);
    }
    #pragma unroll
    for (int o = 16; o; o >>= 1) s += __shfl_xor_sync(0xffffffffu, s, o);
    int lane = threadIdx.x & 31, w = threadIdx.x >> 5;
    if (lane == 0) wsum[w] = s;
    __syncthreads();
    if (threadIdx.x < 8) {
        s = wsum[threadIdx.x];
        #pragma unroll
        for (int o = 4; o; o >>= 1) s += __shfl_xor_sync(0xffu, s, o);
        if (threadIdx.x == 0) atomicAdd(&d_acc, s);
    }
}

__global__ void finalize_kernel(float* out) {
    *out = (float)(d_acc / (double)TOTAL);
}

// ---------------------------------------------------------------------------
extern "C" void kernel_launch(void* const* d_in, const int* in_sizes, int n_in,
                              void* d_out, int out_size) {
    const float* pred   = (const float*)d_in[0];
    const float* target = (const float*)d_in[1];
    float* out = (float*)d_out;

    init_kernel<<<1, 32>>>();
    col_pass_kernel<<<IMGS * 8, 32>>>(target);
    row_pass_kernel<<<IMGS * H, W>>>();
    reduce_kernel<<<512, 256>>>(pred);
    finalize_kernel<<<1, 1>>>(out);
}

// round 2
// speedup vs baseline: 1.6270x; 1.6270x over previous
#include <cuda_runtime.h>
#include <math.h>

#define IMGS  16
#define H     256
#define W     256
#define NPIX  (H * W)            // 65536
#define TOTAL (IMGS * NPIX)      // 1048576
#define INFV  1.0e6f
#define BIGF  3.0e37f

// ---- scratch (static __device__ arrays; allocation-free per harness rules) ----
__device__ float  g_fg[TOTAL];     // squared vertical distance, EDT(mask)
__device__ float  g_bg[TOTAL];     // squared vertical distance, EDT(1-mask)
__device__ float  d_maxabs[IMGS];
__device__ int    d_counts[IMGS];
__device__ double d_S[IMGS];       // per-image sum of prob * sd_unnormalized

// ---------------------------------------------------------------------------
__global__ void init_kernel() {
    int t = threadIdx.x;
    if (t < IMGS) { d_maxabs[t] = 0.0f; d_counts[t] = 0; d_S[t] = 0.0; }
}

// ---------------------------------------------------------------------------
// Vertical two-pass scan (both masks in one go). One warp handles 32 columns
// of one image. grid = IMGS * 8 blocks, 32 threads.
__global__ void col_pass_kernel(const float* __restrict__ target) {
    int b     = blockIdx.x >> 3;
    int chunk = blockIdx.x & 7;
    int x     = chunk * 32 + threadIdx.x;

    const float* m  = target + b * NPIX + x;
    float*       gf = g_fg   + b * NPIX + x;
    float*       gb = g_bg   + b * NPIX + x;

    float cf = INFV, cb = INFV;
    int cnt = 0;
    #pragma unroll 8
    for (int y = 0; y < H; y++) {
        float mv = m[y * W];
        bool  fg = (mv > 0.5f);
        cnt += fg ? 1 : 0;
        cf = fminf(fg ? INFV : 0.0f, cf + 1.0f);
        cb = fminf(fg ? 0.0f : INFV, cb + 1.0f);
        gf[y * W] = cf;
        gb[y * W] = cb;
    }
    cf = INFV; cb = INFV;
    #pragma unroll 8
    for (int y = H - 1; y >= 0; y--) {
        float mv = m[y * W];
        bool  fg = (mv > 0.5f);
        cf = fminf(fg ? INFV : 0.0f, cf + 1.0f);
        cb = fminf(fg ? 0.0f : INFV, cb + 1.0f);
        float df = fminf(cf, gf[y * W]);  gf[y * W] = df * df;
        float db = fminf(cb, gb[y * W]);  gb[y * W] = db * db;
    }
    // warp-reduce foreground count
    #pragma unroll
    for (int o = 16; o; o >>= 1) cnt += __shfl_xor_sync(0xffffffffu, cnt, o);
    if (threadIdx.x == 0) atomicAdd(&d_counts[b], cnt);
}

// ---------------------------------------------------------------------------
// Fused row min-plus + sigmoid + per-image reduction.
// dt2[x] = min_q g_c[q] + (x-q)^2, where c is the pixel's own class
// (fg pixel only needs the fg transform: its bg-transform distance is 0).
// Windowed to |x-q| <= 32 with an exactness guard (excluded q contribute
// >= 33^2 = 1089, so windowed min <= 1089 is provably exact; else rare
// per-thread full-row fallback).
// One block per (image,row). 256 threads, thread x produces one pixel.
__global__ void row_fused_kernel(const float* __restrict__ pred) {
    int b    = blockIdx.x >> 8;
    int y    = blockIdx.x & 255;
    int base = b * NPIX + y * W;
    int x    = threadIdx.x;

    __shared__ float shf[W + 64];
    __shared__ float shb[W + 64];
    __shared__ float wmax[8];
    __shared__ float wsum[8];

    float gf = g_fg[base + x];
    float gb = g_bg[base + x];
    shf[x + 32] = gf;
    shb[x + 32] = gb;
    if (x < 32) {
        shf[x] = BIGF;          shb[x] = BIGF;
        shf[x + W + 32] = BIGF; shb[x + W + 32] = BIGF;
    }
    __syncthreads();

    bool fg = (gf > 0.0f);              // fg pixel <=> not a seed of fg transform
    const float* h = fg ? shf : shb;    // only one transform matters per pixel

    float bmin = BIGF;
    #pragma unroll
    for (int j = 0; j < 65; j++) {      // q = x + (j-32), offset^2 is a literal
        float kk = (float)((j - 32) * (j - 32));
        bmin = fminf(bmin, h[x + j] + kk);
    }
    if (bmin > 1089.0f) {               // exactness fallback (never taken here)
        for (int q = 0; q < W; q++) {
            float dx = (float)(x - q);
            bmin = fminf(bmin, fmaf(dx, dx, h[q + 32]));
        }
    }

    float sd = sqrtf(bmin);
    if (fg) sd = -sd;

    float p    = pred[base + x];
    float prob = 1.0f / (1.0f + expf(-p));
    float term = prob * sd;
    float a    = fabsf(sd);

    #pragma unroll
    for (int o = 16; o; o >>= 1) {
        a    = fmaxf(a, __shfl_xor_sync(0xffffffffu, a, o));
        term +=         __shfl_xor_sync(0xffffffffu, term, o);
    }
    int lane = x & 31, w = x >> 5;
    if (lane == 0) { wmax[w] = a; wsum[w] = term; }
    __syncthreads();
    if (x == 0) {
        float  mx = wmax[0];
        double s  = (double)wsum[0];
        #pragma unroll
        for (int i = 1; i < 8; i++) { mx = fmaxf(mx, wmax[i]); s += (double)wsum[i]; }
        atomicMax((int*)&d_maxabs[b], __float_as_int(mx));   // non-neg floats order as ints
        atomicAdd(&d_S[b], s);
    }
}

// ---------------------------------------------------------------------------
__global__ void finalize_kernel(float* out) {
    double acc = 0.0;
    for (int b = 0; b < IMGS; b++) {
        int c = d_counts[b];
        if (c > 0 && c < NPIX)
            acc += d_S[b] / ((double)d_maxabs[b] + 1e-6);
    }
    *out = (float)(acc / (double)TOTAL);
}

// ---------------------------------------------------------------------------
extern "C" void kernel_launch(void* const* d_in, const int* in_sizes, int n_in,
                              void* d_out, int out_size) {
    const float* pred   = (const float*)d_in[0];
    const float* target = (const float*)d_in[1];
    float* out = (float*)d_out;

    init_kernel<<<1, 32>>>();
    col_pass_kernel<<<IMGS * 8, 32>>>(target);
    row_fused_kernel<<<IMGS * H, W>>>(pred);
    finalize_kernel<<<1, 1>>>(out);
}

// round 3
// speedup vs baseline: 2.6570x; 1.6331x over previous
#include <cuda_runtime.h>
#include <math.h>

#define IMGS  16
#define H     256
#define W     256
#define NPIX  (H * W)            // 65536
#define TOTAL (IMGS * NPIX)      // 1048576
#define INFV  1.0e6f
#define BIGF  3.0e37f
#define RWIN  4                  // min-plus window radius
#define GUARD 25.0f              // (RWIN+1)^2 exactness guard

// ---- scratch (static __device__ arrays; allocation-free per harness rules) ----
__device__ float  s_buf[TOTAL];    // signed squared vertical distance: +v^2 (fg) / -v^2 (bg)
__device__ float  d_maxabs[IMGS];
__device__ int    d_counts[IMGS];
__device__ double d_S[IMGS];       // per-image sum of prob * sd_unnormalized
__device__ unsigned int d_done;    // completion counter for fused finalize

// ---------------------------------------------------------------------------
// Vertical pass: per-pixel distance to nearest OPPOSITE-class pixel in its
// column (exactly reconstructs both EDT seeds: g_fg = fg ? v^2 : 0,
// g_bg = fg ? 0 : v^2). Integer tracker chains; forward temporaries + class
// bits staged in shared. One warp = 32 columns. grid = IMGS*8, block = 32.
__global__ void col_pass_kernel(const float* __restrict__ target) {
    __shared__ unsigned short dfwd[H * 32];
    __shared__ unsigned char  cls[H * 32];

    int b     = blockIdx.x >> 3;
    int chunk = blockIdx.x & 7;
    int t     = threadIdx.x;
    int x     = chunk * 32 + t;

    const float* m  = target + b * NPIX + x;
    float*       sb = s_buf  + b * NPIX + x;

    int lastf = -1000000, lastb = -1000000;
    int cnt = 0;
    #pragma unroll 8
    for (int y = 0; y < H; y++) {
        bool fg = (m[y * W] > 0.5f);
        cnt += fg ? 1 : 0;
        int dopp = y - (fg ? lastb : lastf);         // dist to opposite above
        lastf = fg ? y : lastf;
        lastb = fg ? lastb : y;
        dfwd[y * 32 + t] = (unsigned short)(dopp > 60000 ? 60000 : dopp);
        cls [y * 32 + t] = fg ? 1 : 0;
    }
    int nextf = 1000000, nextb = 1000000;
    #pragma unroll 8
    for (int y = H - 1; y >= 0; y--) {
        bool fg = (cls[y * 32 + t] != 0);
        int dn = (fg ? nextb : nextf) - y;           // dist to opposite below
        nextf = fg ? y : nextf;
        nextb = fg ? nextb : y;
        int df = (int)dfwd[y * 32 + t];
        int dv = dn < df ? dn : df;
        float v = (dv > 255) ? INFV : (float)dv;
        float v2 = v * v;                            // exact (<=65025 or 1e12)
        sb[y * W] = fg ? v2 : -v2;
    }
    #pragma unroll
    for (int o = 16; o; o >>= 1) cnt += __shfl_xor_sync(0xffffffffu, cnt, o);
    if (t == 0) atomicAdd(&d_counts[b], cnt);
}

// ---------------------------------------------------------------------------
// Fused row min-plus + sigmoid + per-image reduction + last-block finalize.
// For pixel x of class c: dt2 = min_q g_c[q] + (x-q)^2 with g_c[q] =
// max(+-s[q], 0). Windowed |x-q|<=RWIN with exactness guard; rare exact
// full-row fallback. One block per (image,row), 256 threads.
__global__ void row_fused_kernel(const float* __restrict__ pred, float* __restrict__ out) {
    int b    = blockIdx.x >> 8;
    int y    = blockIdx.x & 255;
    int base = b * NPIX + y * W;
    int x    = threadIdx.x;

    __shared__ float shf[W + 2 * RWIN];
    __shared__ float shb[W + 2 * RWIN];
    __shared__ float wmax[8];
    __shared__ float wsum[8];
    __shared__ int   is_last;

    float s = s_buf[base + x];
    shf[x + RWIN] = fmaxf(s, 0.0f);    // g_fg
    shb[x + RWIN] = fmaxf(-s, 0.0f);   // g_bg
    if (x < RWIN) {
        shf[x] = BIGF;               shb[x] = BIGF;
        shf[x + W + RWIN] = BIGF;    shb[x + W + RWIN] = BIGF;
    }
    __syncthreads();

    bool fg = (s > 0.0f);
    const float* h = fg ? shf : shb;

    float bmin = BIGF;
    #pragma unroll
    for (int j = 0; j <= 2 * RWIN; j++) {       // q = x + (j-RWIN)
        float kk = (float)((j - RWIN) * (j - RWIN));
        bmin = fminf(bmin, h[x + j] + kk);
    }
    if (bmin > GUARD) {                          // rare exact fallback
        for (int q = 0; q < W; q++) {
            float dx = (float)(x - q);
            bmin = fminf(bmin, fmaf(dx, dx, h[q + RWIN]));
        }
    }

    float sd = sqrtf(bmin);
    if (fg) sd = -sd;

    float p    = pred[base + x];
    float prob = 1.0f / (1.0f + expf(-p));
    float term = prob * sd;
    float a    = fabsf(sd);

    #pragma unroll
    for (int o = 16; o; o >>= 1) {
        a    = fmaxf(a, __shfl_xor_sync(0xffffffffu, a, o));
        term +=         __shfl_xor_sync(0xffffffffu, term, o);
    }
    int lane = x & 31, w = x >> 5;
    if (lane == 0) { wmax[w] = a; wsum[w] = term; }
    __syncthreads();

    if (x == 0) {
        float  mx = wmax[0];
        double sm = (double)wsum[0];
        #pragma unroll
        for (int i = 1; i < 8; i++) { mx = fmaxf(mx, wmax[i]); sm += (double)wsum[i]; }
        atomicMax((int*)&d_maxabs[b], __float_as_int(mx));  // non-neg floats order as ints
        atomicAdd(&d_S[b], sm);
        __threadfence();
        unsigned int old = atomicAdd(&d_done, 1u);
        is_last = (old == (unsigned int)(IMGS * H - 1)) ? 1 : 0;
    }
    __syncthreads();

    if (is_last) {
        __threadfence();
        double contrib = 0.0;
        if (x < IMGS) {
            int    c  = __ldcg(&d_counts[x]);
            float  mx = __ldcg(&d_maxabs[x]);
            double S  = __ldcg(&d_S[x]);
            if (c > 0 && c < NPIX)
                contrib = S / ((double)mx + 1e-6);
        }
        if (x < 32) {
            #pragma unroll
            for (int o = 16; o; o >>= 1)
                contrib += __shfl_xor_sync(0xffffffffu, contrib, o);
            if (x == 0) *out = (float)(contrib / (double)TOTAL);
        }
        // reset all accumulators for the next graph replay
        if (x < IMGS) { d_S[x] = 0.0; d_maxabs[x] = 0.0f; d_counts[x] = 0; }
        if (x == 0)   d_done = 0u;
    }
}

// ---------------------------------------------------------------------------
extern "C" void kernel_launch(void* const* d_in, const int* in_sizes, int n_in,
                              void* d_out, int out_size) {
    const float* pred   = (const float*)d_in[0];
    const float* target = (const float*)d_in[1];
    float* out = (float*)d_out;

    col_pass_kernel<<<IMGS * 8, 32>>>(target);
    row_fused_kernel<<<IMGS * H, W>>>(pred, out);
}

// round 4
// speedup vs baseline: 2.8495x; 1.0725x over previous
#include <cuda_runtime.h>
#include <math.h>

#define IMGS  16
#define H     256
#define W     256
#define NPIX  (H * W)            // 65536
#define TOTAL (IMGS * NPIX)      // 1048576
#define BIG2  1.0e12f            // (1e6)^2 for "no seed in column"
#define BIGF  3.0e37f
#define RWIN  4                  // min-plus window radius
#define GUARD 25.0f              // (RWIN+1)^2 exactness guard
#define RPB   4                  // rows per block in the row kernel

// ---- scratch (static __device__ arrays; allocation-free per harness rules) ----
__device__ float  s_buf[TOTAL];    // signed squared vertical distance: +v^2 (fg) / -v^2 (bg)
__device__ float  d_maxabs[IMGS];
__device__ int    d_counts[IMGS];
__device__ double d_S[IMGS];       // per-image sum of prob * sd_unnormalized
__device__ unsigned int d_done;    // completion counter for fused finalize

// ---------------------------------------------------------------------------
// Vertical pass. Phase 0: load the whole column as INDEPENDENT loads (full
// MLP) into an fg bitmask (8 words/thread). Phase 1/2: forward + backward
// nearest-opposite scans over register bits (SEL chains), forward distances
// staged in shared. One warp = 32 columns. grid = IMGS*8, block = 32.
__global__ void col_pass_kernel(const float* __restrict__ target) {
    __shared__ int dfwd[H * 32];

    int b     = blockIdx.x >> 3;
    int chunk = blockIdx.x & 7;
    int t     = threadIdx.x;
    int x     = chunk * 32 + t;

    const float* m  = target + b * NPIX + x;
    float*       sb = s_buf  + b * NPIX + x;

    unsigned int bits[8];
    #pragma unroll
    for (int k = 0; k < 8; k++) {
        unsigned int wrd = 0;
        #pragma unroll
        for (int j = 0; j < 32; j++) {
            if (m[(k * 32 + j) * W] > 0.5f) wrd |= (1u << j);
        }
        bits[k] = wrd;
    }
    int cnt = 0;
    #pragma unroll
    for (int k = 0; k < 8; k++) cnt += __popc(bits[k]);

    int lastf = -1000000, lastb = -1000000;
    #pragma unroll 8
    for (int y = 0; y < H; y++) {
        bool fg = (bits[y >> 5] >> (y & 31)) & 1;
        int dopp = y - (fg ? lastb : lastf);   // dist to opposite-class above
        lastf = fg ? y : lastf;
        lastb = fg ? lastb : y;
        dfwd[y * 32 + t] = dopp;
    }
    int nextf = 1000000, nextb = 1000000;
    #pragma unroll 8
    for (int y = H - 1; y >= 0; y--) {
        bool fg = (bits[y >> 5] >> (y & 31)) & 1;
        int dn = (fg ? nextb : nextf) - y;     // dist to opposite-class below
        nextf = fg ? y : nextf;
        nextb = fg ? nextb : y;
        int df = dfwd[y * 32 + t];
        int dv = dn < df ? dn : df;
        if (dv > 256) dv = 256;                // clamp BEFORE squaring (no overflow)
        float v2 = (dv > 255) ? BIG2 : (float)(dv * dv);
        sb[y * W] = fg ? v2 : -v2;
    }
    #pragma unroll
    for (int o = 16; o; o >>= 1) cnt += __shfl_xor_sync(0xffffffffu, cnt, o);
    if (t == 0) atomicAdd(&d_counts[b], cnt);
}

// ---------------------------------------------------------------------------
// Fused row min-plus + sigmoid + per-image reduction + last-block finalize.
// 4 rows per block, 4 pixels per thread (all float4). Both class minima are
// computed (alu pipe has headroom) and selected per pixel -> no divergence.
// Windowed |x-q|<=RWIN with exactness guard; rare exact full-row fallback.
__global__ void row_fused_kernel(const float* __restrict__ pred, float* __restrict__ out) {
    int blk  = blockIdx.x;
    int b    = blk >> 6;                 // 64 blocks per image (H/RPB)
    int y0   = (blk & 63) * RPB;
    int tid  = threadIdx.x;
    int r    = tid >> 6;                 // row within block: 0..3
    int c    = tid & 63;                 // pixel-quad within row: 0..63
    int base = b * NPIX + (y0 + r) * W;
    int x0   = c * 4;

    __shared__ float shf[RPB][W + 2 * RWIN];
    __shared__ float shb[RPB][W + 2 * RWIN];
    __shared__ float wmax[8];
    __shared__ float wsum[8];
    __shared__ int   is_last;

    float4 s4 = *(const float4*)(s_buf + base + x0);
    *(float4*)&shf[r][x0 + RWIN] =
        make_float4(fmaxf(s4.x, 0.f), fmaxf(s4.y, 0.f), fmaxf(s4.z, 0.f), fmaxf(s4.w, 0.f));
    *(float4*)&shb[r][x0 + RWIN] =
        make_float4(fmaxf(-s4.x, 0.f), fmaxf(-s4.y, 0.f), fmaxf(-s4.z, 0.f), fmaxf(-s4.w, 0.f));
    if (c < 2) {
        int o = (c == 0) ? 0 : (W + RWIN);
        *(float4*)&shf[r][o] = make_float4(BIGF, BIGF, BIGF, BIGF);
        *(float4*)&shb[r][o] = make_float4(BIGF, BIGF, BIGF, BIGF);
    }
    __syncthreads();

    // Window values for this thread's 4 pixels: shared idx x0 .. x0+11.
    float uf[12], ub[12];
    #pragma unroll
    for (int i = 0; i < 3; i++) {
        float4 a = *(const float4*)&shf[r][x0 + 4 * i];
        float4 d = *(const float4*)&shb[r][x0 + 4 * i];
        uf[4*i] = a.x; uf[4*i+1] = a.y; uf[4*i+2] = a.z; uf[4*i+3] = a.w;
        ub[4*i] = d.x; ub[4*i+1] = d.y; ub[4*i+2] = d.z; ub[4*i+3] = d.w;
    }
    float4 p4 = *(const float4*)(pred + base + x0);
    float pr[4] = {p4.x, p4.y, p4.z, p4.w};
    float sv[4] = {s4.x, s4.y, s4.z, s4.w};

    float term = 0.f, amax = 0.f;
    #pragma unroll
    for (int p = 0; p < 4; p++) {
        float bf = BIGF, bb = BIGF;
        #pragma unroll
        for (int j = 0; j < 9; j++) {          // q = x + (j-RWIN), kk is a literal
            float kk = (float)((j - RWIN) * (j - RWIN));
            bf = fminf(bf, uf[p + j] + kk);
            bb = fminf(bb, ub[p + j] + kk);
        }
        bool  fg   = (sv[p] > 0.f);
        float bmin = fg ? bf : bb;
        if (bmin > GUARD) {                    // rare exact full-row fallback
            const float* hh = fg ? &shf[r][RWIN] : &shb[r][RWIN];
            float xp = (float)(x0 + p);
            bmin = BIGF;
            for (int q = 0; q < W; q++) {
                float dx = xp - (float)q;
                bmin = fminf(bmin, fmaf(dx, dx, hh[q]));
            }
        }
        float sd = sqrtf(bmin);
        if (fg) sd = -sd;
        float prob = __fdividef(1.f, 1.f + __expf(-pr[p]));
        term += prob * sd;
        amax  = fmaxf(amax, fabsf(sd));
    }

    #pragma unroll
    for (int o = 16; o; o >>= 1) {
        amax = fmaxf(amax, __shfl_xor_sync(0xffffffffu, amax, o));
        term +=            __shfl_xor_sync(0xffffffffu, term, o);
    }
    int lane = tid & 31, w = tid >> 5;
    if (lane == 0) { wmax[w] = amax; wsum[w] = term; }
    __syncthreads();

    if (tid == 0) {
        float  mx = wmax[0];
        double sm = (double)wsum[0];
        #pragma unroll
        for (int i = 1; i < 8; i++) { mx = fmaxf(mx, wmax[i]); sm += (double)wsum[i]; }
        atomicMax((int*)&d_maxabs[b], __float_as_int(mx));  // non-neg floats order as ints
        atomicAdd(&d_S[b], sm);
        __threadfence();
        unsigned int old = atomicAdd(&d_done, 1u);
        is_last = (old == (unsigned int)(IMGS * (H / RPB) - 1)) ? 1 : 0;
    }
    __syncthreads();

    if (is_last) {
        __threadfence();
        double contrib = 0.0;
        if (tid < IMGS) {
            int    cc = __ldcg(&d_counts[tid]);
            float  mx = __ldcg(&d_maxabs[tid]);
            double S  = __ldcg(&d_S[tid]);
            if (cc > 0 && cc < NPIX)
                contrib = S / ((double)mx + 1e-6);
        }
        if (tid < 32) {
            #pragma unroll
            for (int o = 16; o; o >>= 1)
                contrib += __shfl_xor_sync(0xffffffffu, contrib, o);
            if (tid == 0) *out = (float)(contrib / (double)TOTAL);
        }
        // reset accumulators for the next graph replay
        if (tid < IMGS) { d_S[tid] = 0.0; d_maxabs[tid] = 0.0f; d_counts[tid] = 0; }
        if (tid == 0)   d_done = 0u;
    }
}

// ---------------------------------------------------------------------------
extern "C" void kernel_launch(void* const* d_in, const int* in_sizes, int n_in,
                              void* d_out, int out_size) {
    const float* pred   = (const float*)d_in[0];
    const float* target = (const float*)d_in[1];
    float* out = (float*)d_out;

    col_pass_kernel<<<IMGS * 8, 32>>>(target);
    row_fused_kernel<<<IMGS * (H / RPB), 256>>>(pred, out);
}

// round 7
// speedup vs baseline: 5.6424x; 1.9801x over previous
#include <cuda_runtime.h>
#include <math.h>

#define IMGS  16
#define H     256
#define W     256
#define NPIX  (H * W)            // 65536
#define TOTAL (IMGS * NPIX)      // 1048576
#define BIG2  1.0e12f            // (1e6)^2 for "no opposite pixel in column"
#define BIGF  3.0e37f
#define RWIN  4
#define GUARD 25.0f              // (RWIN+1)^2 exactness guard
#define RPB   4                  // rows per block in the row kernel
#define NROWBLK (IMGS * H / RPB) // 1024

// ---- scratch (static __device__ arrays; allocation-free per harness rules) ----
__device__ float  s_buf[TOTAL];    // signed squared vertical distance: +v^2 (fg) / -v^2 (bg)
__device__ float  d_maxabs[IMGS];
__device__ int    d_counts[IMGS];
__device__ double d_S[IMGS];
__device__ unsigned int d_done;    // completion counter for fused finalize

__device__ __forceinline__ float sqrt_approx(float x) {
    float r;
    asm("sqrt.approx.f32 %0, %1;" : "=f"(r) : "f"(x));
    return r;
}

// ---------------------------------------------------------------------------
// Vertical EDT pass. 128 blocks x 256 threads: each thread owns a 32-row
// segment of one column. Phase 0: 32 independent mask loads -> bitmask (full
// MLP). Segment summaries (clz/ffs) combine across segments in shared, then
// two 32-step fully unrolled SEL chains per thread. Output: signed v^2.
__global__ void col_pass_kernel(const float* __restrict__ target) {
    __shared__ int sHiF[8][32], sHiB[8][32];
    __shared__ int sLoF[8][32], sLoB[8][32];

    int blk   = blockIdx.x;
    int tid   = threadIdx.x;
    int b     = blk >> 3;
    int chunk = blk & 7;
    int t     = tid & 31;      // local column
    int w     = tid >> 5;      // 32-row segment
    int x     = chunk * 32 + t;
    int ybase = w * 32;

    const float* m = target + b * NPIX + x;
    unsigned word = 0;
    #pragma unroll
    for (int j = 0; j < 32; j++)
        if (m[(ybase + j) * W] > 0.5f) word |= (1u << j);
    int cnt = __popc(word);

    unsigned nw = ~word;
    sHiF[w][t] = word ? (ybase + 31 - __clz(word)) : -1000000;
    sHiB[w][t] = nw   ? (ybase + 31 - __clz(nw))   : -1000000;
    sLoF[w][t] = word ? (ybase + __ffs(word) - 1)  :  1000000;
    sLoB[w][t] = nw   ? (ybase + __ffs(nw) - 1)    :  1000000;
    __syncthreads();

    int lastf = -1000000, lastb = -1000000;
    for (int w2 = 0; w2 < w; w2++) {
        lastf = max(lastf, sHiF[w2][t]);
        lastb = max(lastb, sHiB[w2][t]);
    }
    int nextf = 1000000, nextb = 1000000;
    for (int w2 = w + 1; w2 < 8; w2++) {
        nextf = min(nextf, sLoF[w2][t]);
        nextb = min(nextb, sLoB[w2][t]);
    }

    // forward chain: distance to nearest opposite-class pixel above (u16 packed)
    unsigned pk[16];
    #pragma unroll
    for (int j = 0; j < 32; j++) {
        int  y  = ybase + j;
        bool fg = (word >> j) & 1;
        int  da = y - (fg ? lastb : lastf);
        if (da > 1000) da = 1000;
        if (j & 1) pk[j >> 1] |= ((unsigned)da << 16);
        else       pk[j >> 1]  =  (unsigned)da;
        if (fg) lastf = y; else lastb = y;
    }
    // backward chain + combine + store signed v^2
    float* sbp = s_buf + b * NPIX + x;
    #pragma unroll
    for (int j = 31; j >= 0; j--) {
        int  y  = ybase + j;
        bool fg = (word >> j) & 1;
        int  db = (fg ? nextb : nextf) - y;
        if (fg) nextf = y; else nextb = y;
        int da = (int)((pk[j >> 1] >> ((j & 1) * 16)) & 0xffffu);
        int d  = min(da, db);
        float v2 = (d > 255) ? BIG2 : (float)(d * d);
        sbp[y * W] = fg ? v2 : -v2;
    }

    #pragma unroll
    for (int o = 16; o; o >>= 1) cnt += __shfl_xor_sync(0xffffffffu, cnt, o);
    if (t == 0) atomicAdd(&d_counts[b], cnt);
}

// ---------------------------------------------------------------------------
// Fused row min-plus + sigmoid + per-image reduction + last-block finalize.
// 4 rows per block, 4 pixels per thread. Single SIGNED shared array; candidate
// value for a pixel of class sign sg:  g_c[q] + k^2 = max(sg*s[q] + k^2, k^2).
// Window |x-q| <= 4 with exactness guard 25; edge-replicated halo entries are
// dominated (monotone in k^2) so the window stays exact; rare exact fallback.
__global__ void row_fused_kernel(const float* __restrict__ pred, float* __restrict__ out) {
    int blk  = blockIdx.x;
    int b    = blk >> 6;                 // 64 blocks per image
    int y0   = (blk & 63) * RPB;
    int tid  = threadIdx.x;
    int r    = tid >> 6;                 // row within block: 0..3
    int c    = tid & 63;                 // pixel-quad within row
    int base = b * NPIX + (y0 + r) * W;
    int x0   = c * 4;

    __shared__ float sh[RPB][W + 8];     // signed s tiles, +4 halo each side
    __shared__ float wred[16];           // 8 warp maxes + 8 warp sums
    __shared__ int   is_last;

    float4 s4 = *(const float4*)(s_buf + base + x0);
    *(float4*)&sh[r][x0 + 4] = s4;
    if (c == 0)  { sh[r][0] = s4.x; sh[r][1] = s4.x; sh[r][2] = s4.x; sh[r][3] = s4.x; }
    if (c == 63) { sh[r][W+4] = s4.w; sh[r][W+5] = s4.w; sh[r][W+6] = s4.w; sh[r][W+7] = s4.w; }
    float4 p4 = *(const float4*)(pred + base + x0);
    __syncthreads();

    float u[12];
    #pragma unroll
    for (int i = 0; i < 3; i++) {
        float4 a = *(const float4*)&sh[r][x0 + 4 * i];
        u[4*i] = a.x; u[4*i+1] = a.y; u[4*i+2] = a.z; u[4*i+3] = a.w;
    }
    float pr[4] = {p4.x, p4.y, p4.z, p4.w};

    float term = 0.f, amax = 0.f;
    #pragma unroll
    for (int p = 0; p < 4; p++) {
        float s_own = u[p + 4];
        float sg    = (s_own > 0.f) ? 1.f : -1.f;       // +1 fg, -1 bg
        float bmin  = BIGF;
        #pragma unroll
        for (int j = 0; j < 9; j++) {                   // q = x + (j-4)
            float kk = (float)((j - 4) * (j - 4));
            bmin = fminf(bmin, fmaxf(fmaf(sg, u[p + j], kk), kk));
        }
        if (bmin > GUARD) {                             // rare exact full-row fallback
            float xp = (float)(x0 + p);
            bmin = BIGF;
            #pragma unroll 1
            for (int q = 0; q < W; q++) {
                float dx = xp - (float)q;
                float kk = dx * dx;
                bmin = fminf(bmin, fmaxf(fmaf(sg, sh[r][q + 4], kk), kk));
            }
        }
        float sd   = sqrt_approx(bmin);                 // bmin >= 1 always
        amax       = fmaxf(amax, sd);
        float prob = __fdividef(1.f, 1.f + __expf(-pr[p]));
        float sds  = (s_own > 0.f) ? -sd : sd;          // signed distance
        term       = fmaf(prob, sds, term);
    }

    #pragma unroll
    for (int o = 16; o; o >>= 1) {
        amax = fmaxf(amax, __shfl_xor_sync(0xffffffffu, amax, o));
        term +=            __shfl_xor_sync(0xffffffffu, term, o);
    }
    int lane = tid & 31, wp = tid >> 5;
    if (lane == 0) { wred[wp] = amax; wred[8 + wp] = term; }
    __syncthreads();

    if (tid == 0) {
        float  mx = wred[0];
        double sm = (double)wred[8];
        #pragma unroll
        for (int i = 1; i < 8; i++) { mx = fmaxf(mx, wred[i]); sm += (double)wred[8 + i]; }
        atomicMax((int*)&d_maxabs[b], __float_as_int(mx));   // non-neg floats order as ints
        atomicAdd(&d_S[b], sm);
        __threadfence();
        unsigned int old = atomicAdd(&d_done, 1u);
        is_last = (old == (unsigned)(NROWBLK - 1)) ? 1 : 0;
    }
    __syncthreads();

    if (is_last) {
        __threadfence();
        double contrib = 0.0;
        if (tid < IMGS) {
            int    cc = __ldcg(&d_counts[tid]);
            float  mx = __ldcg(&d_maxabs[tid]);
            double S  = __ldcg(&d_S[tid]);
            if (cc > 0 && cc < NPIX)
                contrib = S / ((double)mx + 1e-6);
        }
        if (tid < 32) {
            #pragma unroll
            for (int o = 16; o; o >>= 1)
                contrib += __shfl_xor_sync(0xffffffffu, contrib, o);
            if (tid == 0) *out = (float)(contrib / (double)TOTAL);
        }
        // reset accumulators for the next graph replay
        if (tid < IMGS) { d_S[tid] = 0.0; d_maxabs[tid] = 0.0f; d_counts[tid] = 0; }
        if (tid == 0)   d_done = 0u;
    }
}

// ---------------------------------------------------------------------------
extern "C" void kernel_launch(void* const* d_in, const int* in_sizes, int n_in,
                              void* d_out, int out_size) {
    const float* pred   = (const float*)d_in[0];
    const float* target = (const float*)d_in[1];
    float* out = (float*)d_out;

    col_pass_kernel<<<IMGS * 8, 256>>>(target);
    row_fused_kernel<<<NROWBLK, 256>>>(pred, out);
}